// round 2
// baseline (speedup 1.0000x reference)
#include <cuda_runtime.h>
#include <cuda_bf16.h>
#include <cstdint>

#define SEQL  256
#define BATCHN 64
#define EMBD  256
#define HID   512
#define OUTD  18
#define MROWS (SEQL*BATCHN)   // 16384

// ---------------- scratch (static device arrays; no allocation) ----------------
__device__ float g_post_emb[MROWS * EMBD];            // 16 MB
__device__ float g_xp0[2 * SEQL * BATCHN * HID];      // 64 MB  [d][s][b][h]
__device__ float g_h0 [MROWS * 2 * HID];              // 64 MB  [s][b][2H]
__device__ float g_xp1[2 * SEQL * BATCHN * HID];      // 64 MB
__device__ float g_h1 [MROWS * 2 * HID];              // 64 MB
__device__ float g_hsc[2][2][BATCHN][HID];            // 512 KB [buf][dir][b][h]

// =====================================================================
// Generic fp32 SIMT GEMM: C[M,N] = A[M,K] * Bw[N,K]^T + bias
// BM=128, BN=64, BK=16, 256 threads, thread tile 8x4, double buffered.
// GATHER: A row m comes from gtab[gidx[m]*K ...]
// SCATTER: write C into [d][s][b][h] layout (d=n>>9, h=n&511, s=m>>6, b=m&63)
// =====================================================================
template<int GATHER, int SCATTER, int NBIAS>
__global__ void __launch_bounds__(256, 2)
gemm_k(const float* __restrict__ A, const float* __restrict__ Bw,
       const float* __restrict__ bias1, const float* __restrict__ bias2,
       float* __restrict__ C,
       const int* __restrict__ gidx, const float* __restrict__ gtab,
       int N, int K)
{
    constexpr int BM = 128, BN = 64, BK = 16;
    __shared__ float As[2][BK][BM];
    __shared__ float Bs[2][BK][BN];

    const int tid   = threadIdx.x;
    const int mBase = blockIdx.y * BM;
    const int nBase = blockIdx.x * BN;
    const int tx = tid & 15;      // n-frag (4 cols)
    const int ty = tid >> 4;      // m-frag (8 rows)

    // load mapping
    const int ar0 = tid >> 2;             // 0..63  (rows ar0 and ar0+64)
    const int ak4 = (tid & 3) * 4;        // k offset within BK
    const int br  = tid >> 2;             // 0..63

    const int row0 = mBase + ar0;
    const int row1 = row0 + 64;
    const float* arp0;
    const float* arp1;
    if (GATHER) {
        arp0 = gtab + (size_t)gidx[row0] * K;
        arp1 = gtab + (size_t)gidx[row1] * K;
    } else {
        arp0 = A + (size_t)row0 * K;
        arp1 = A + (size_t)row1 * K;
    }
    const int   brow = nBase + br;
    const float* brp = (brow < N) ? (Bw + (size_t)brow * K) : nullptr;

    const int KT = K / BK;

    float4 a0r, a1r, b0r;

    // prologue: stage 0
    a0r = *reinterpret_cast<const float4*>(arp0 + ak4);
    a1r = *reinterpret_cast<const float4*>(arp1 + ak4);
    b0r = brp ? *reinterpret_cast<const float4*>(brp + ak4) : make_float4(0.f,0.f,0.f,0.f);
    {
        As[0][ak4+0][ar0]    = a0r.x; As[0][ak4+1][ar0]    = a0r.y;
        As[0][ak4+2][ar0]    = a0r.z; As[0][ak4+3][ar0]    = a0r.w;
        As[0][ak4+0][ar0+64] = a1r.x; As[0][ak4+1][ar0+64] = a1r.y;
        As[0][ak4+2][ar0+64] = a1r.z; As[0][ak4+3][ar0+64] = a1r.w;
        Bs[0][ak4+0][br] = b0r.x; Bs[0][ak4+1][br] = b0r.y;
        Bs[0][ak4+2][br] = b0r.z; Bs[0][ak4+3][br] = b0r.w;
    }
    __syncthreads();

    float acc[8][4];
    #pragma unroll
    for (int i = 0; i < 8; i++)
        #pragma unroll
        for (int j = 0; j < 4; j++) acc[i][j] = 0.f;

    #pragma unroll 1
    for (int kt = 0; kt < KT; kt++) {
        const int buf = kt & 1;
        if (kt + 1 < KT) {
            const int ko = (kt + 1) * BK + ak4;
            a0r = *reinterpret_cast<const float4*>(arp0 + ko);
            a1r = *reinterpret_cast<const float4*>(arp1 + ko);
            b0r = brp ? *reinterpret_cast<const float4*>(brp + ko) : make_float4(0.f,0.f,0.f,0.f);
        }
        #pragma unroll
        for (int k = 0; k < BK; k++) {
            float4 af0 = *reinterpret_cast<const float4*>(&As[buf][k][ty * 8]);
            float4 af1 = *reinterpret_cast<const float4*>(&As[buf][k][ty * 8 + 4]);
            float4 bf  = *reinterpret_cast<const float4*>(&Bs[buf][k][tx * 4]);
            float am[8] = {af0.x, af0.y, af0.z, af0.w, af1.x, af1.y, af1.z, af1.w};
            float bn[4] = {bf.x, bf.y, bf.z, bf.w};
            #pragma unroll
            for (int i = 0; i < 8; i++)
                #pragma unroll
                for (int j = 0; j < 4; j++)
                    acc[i][j] = fmaf(am[i], bn[j], acc[i][j]);
        }
        if (kt + 1 < KT) {
            const int nb = (kt + 1) & 1;
            As[nb][ak4+0][ar0]    = a0r.x; As[nb][ak4+1][ar0]    = a0r.y;
            As[nb][ak4+2][ar0]    = a0r.z; As[nb][ak4+3][ar0]    = a0r.w;
            As[nb][ak4+0][ar0+64] = a1r.x; As[nb][ak4+1][ar0+64] = a1r.y;
            As[nb][ak4+2][ar0+64] = a1r.z; As[nb][ak4+3][ar0+64] = a1r.w;
            Bs[nb][ak4+0][br] = b0r.x; Bs[nb][ak4+1][br] = b0r.y;
            Bs[nb][ak4+2][br] = b0r.z; Bs[nb][ak4+3][br] = b0r.w;
            __syncthreads();
        }
    }

    // epilogue
    #pragma unroll
    for (int i = 0; i < 8; i++) {
        const int m = mBase + ty * 8 + i;
        #pragma unroll
        for (int j = 0; j < 4; j++) {
            const int n = nBase + tx * 4 + j;
            if (n < N) {
                float v = acc[i][j];
                if (NBIAS >= 1) v += bias1[n];
                if (NBIAS >= 2) v += bias2[n];
                if (SCATTER) {
                    const int s = m >> 6, b = m & 63, d = n >> 9, h = n & 511;
                    C[(size_t)d * (SEQL * BATCHN * HID) +
                      (size_t)s * (BATCHN * HID) + b * HID + h] = v;
                } else {
                    C[(size_t)m * N + n] = v;
                }
            }
        }
    }
}

// =====================================================================
// Recurrence kernel: 16 clusters of 8 CTAs (128 CTAs total).
// cluster = (dir d, batch-octet g); CTA rank r = 64-output slice.
// W_hh slice [64,512] lives in registers (128 floats per thread).
// h exchanged via L2 (stcg/ldcg) + barrier.cluster per step.
// =====================================================================
__global__ void __cluster_dims__(8, 1, 1) __launch_bounds__(256, 1)
rnn_k(const float* __restrict__ xp,      // [2][SEQL][BATCHN][HID]
      const float* __restrict__ whh,     // [2][HID][HID]
      float* __restrict__ hout)          // [SEQL][BATCHN][2*HID]
{
    const int r   = blockIdx.x & 7;
    const int cid = blockIdx.x >> 3;
    const int d   = cid & 1;
    const int g   = cid >> 1;            // batch octet: batches g*8 .. g*8+7
    const int t   = threadIdx.x;
    const int c   = t >> 6;              // k-chunk 0..3
    const int oo  = t & 63;
    const int orow = r * 64 + oo;
    const int c128 = c * 128;

    // --- load W slice into registers ---
    float W[128];
    const float* wrow = whh + ((size_t)(d * HID + orow)) * HID + c128;
    #pragma unroll
    for (int i = 0; i < 128; i += 4) {
        float4 v = *reinterpret_cast<const float4*>(wrow + i);
        W[i] = v.x; W[i+1] = v.y; W[i+2] = v.z; W[i+3] = v.w;
    }

    // --- zero scratch buf 0 for our (d, batch-octet) slice ---
    float* sc0 = &g_hsc[0][d][g * 8][0];
    #pragma unroll
    for (int i = t * 4; i < 4096; i += 1024)
        *reinterpret_cast<float4*>(sc0 + i) = make_float4(0.f, 0.f, 0.f, 0.f);

    asm volatile("barrier.cluster.arrive.aligned;" ::: "memory");
    asm volatile("barrier.cluster.wait.aligned;"   ::: "memory");

    __shared__ float h_sm[8][HID];
    __shared__ float part[4][64][9];     // pad to 9: conflict-free

    #pragma unroll 1
    for (int step = 0; step < SEQL; step++) {
        const int s = d ? (SEQL - 1 - step) : step;

        // load h_prev [8][512] from L2 scratch into smem
        const float* src = &g_hsc[step & 1][d][g * 8][0];
        #pragma unroll
        for (int i = t * 4; i < 4096; i += 1024) {
            float4 v = __ldcg(reinterpret_cast<const float4*>(src + i));
            *reinterpret_cast<float4*>(&h_sm[0][0] + i) = v;
        }
        __syncthreads();

        // partial dot products: W[orow, c*128 : c*128+128] . h[b, same k range]
        float acc[8] = {0.f,0.f,0.f,0.f,0.f,0.f,0.f,0.f};
        #pragma unroll
        for (int i = 0; i < 128; i += 4) {
            const float w0 = W[i], w1 = W[i+1], w2 = W[i+2], w3 = W[i+3];
            #pragma unroll
            for (int b = 0; b < 8; b++) {
                const float4 hv = *reinterpret_cast<const float4*>(&h_sm[b][c128 + i]);
                acc[b] = fmaf(w0, hv.x, acc[b]);
                acc[b] = fmaf(w1, hv.y, acc[b]);
                acc[b] = fmaf(w2, hv.z, acc[b]);
                acc[b] = fmaf(w3, hv.w, acc[b]);
            }
        }
        #pragma unroll
        for (int b = 0; b < 8; b++) part[c][oo][b] = acc[b];
        __syncthreads();

        // reduce over 4 k-chunks; each thread finalizes 2 of the 512 outputs
        const float* xpb = xp + ((size_t)(d * SEQL + s) * BATCHN) * HID;
        float* scn = &g_hsc[(step + 1) & 1][d][0][0];
        #pragma unroll
        for (int half = 0; half < 2; half++) {
            const int b = (t >> 6) + half * 4;
            float v = part[0][oo][b] + part[1][oo][b] + part[2][oo][b] + part[3][oo][b];
            v += xpb[(size_t)(g * 8 + b) * HID + orow];
            v = fmaxf(v, 0.f);
            __stcg(&scn[(size_t)(g * 8 + b) * HID + orow], v);
            hout[((size_t)s * BATCHN + g * 8 + b) * (2 * HID) + d * HID + orow] = v;
        }

        asm volatile("barrier.cluster.arrive.aligned;" ::: "memory");
        asm volatile("barrier.cluster.wait.aligned;"   ::: "memory");
    }
}

// =====================================================================
extern "C" void kernel_launch(void* const* d_in, const int* in_sizes, int n_in,
                              void* d_out, int out_size)
{
    const int*   text   = (const int*)  d_in[0];
    const float* emb    = (const float*)d_in[1];
    const float* emfc_w = (const float*)d_in[2];
    const float* emfc_b = (const float*)d_in[3];
    const float* w_ih0  = (const float*)d_in[4];
    const float* w_hh0  = (const float*)d_in[5];
    const float* b_ih0  = (const float*)d_in[6];
    const float* b_hh0  = (const float*)d_in[7];
    const float* w_ih1  = (const float*)d_in[8];
    const float* w_hh1  = (const float*)d_in[9];
    const float* b_ih1  = (const float*)d_in[10];
    const float* b_hh1  = (const float*)d_in[11];
    const float* fc_w   = (const float*)d_in[12];
    const float* fc_b   = (const float*)d_in[13];
    float* out = (float*)d_out;

    float *p_pe, *p_xp0, *p_h0, *p_xp1, *p_h1;
    cudaGetSymbolAddress((void**)&p_pe,  g_post_emb);
    cudaGetSymbolAddress((void**)&p_xp0, g_xp0);
    cudaGetSymbolAddress((void**)&p_h0,  g_h0);
    cudaGetSymbolAddress((void**)&p_xp1, g_xp1);
    cudaGetSymbolAddress((void**)&p_h1,  g_h1);

    dim3 blk(256);

    // 1) post_emb = gather(emb_table, text) @ emfc_w^T + emfc_b        [16384,256]
    gemm_k<1,0,1><<<dim3(EMBD/64, MROWS/128), blk>>>(
        nullptr, emfc_w, emfc_b, nullptr, p_pe, text, emb, EMBD, EMBD);

    // 2) xp0[d][s][b][h] = post_emb @ w_ih0^T + (b_ih0+b_hh0)          N=1024,K=256
    gemm_k<0,1,2><<<dim3(1024/64, MROWS/128), blk>>>(
        p_pe, w_ih0, b_ih0, b_hh0, p_xp0, nullptr, nullptr, 1024, EMBD);

    // 3) layer-0 bidirectional recurrence -> h0 [s][b][1024]
    rnn_k<<<128, blk>>>(p_xp0, w_hh0, p_h0);

    // 4) xp1 = h0 @ w_ih1^T + (b_ih1+b_hh1)                            N=1024,K=1024
    gemm_k<0,1,2><<<dim3(1024/64, MROWS/128), blk>>>(
        p_h0, w_ih1, b_ih1, b_hh1, p_xp1, nullptr, nullptr, 1024, 1024);

    // 5) layer-1 recurrence -> h1
    rnn_k<<<128, blk>>>(p_xp1, w_hh1, p_h1);

    // 6) out = h1 @ fc_w^T + fc_b                                      N=18,K=1024
    gemm_k<0,0,1><<<dim3(1, MROWS/128), blk>>>(
        p_h1, fc_w, fc_b, nullptr, out, nullptr, nullptr, OUTD, 1024);
}